// round 4
// baseline (speedup 1.0000x reference)
#include <cuda_runtime.h>
#include <math.h>

typedef unsigned long long u64;

#define B_DIM 8
#define H_DIM 16
#define N_PTS 1024
#define ROWS  8          // rows per thread
#define GROUPS 128       // 128 groups * 8 rows = 1024 rows
#define SLICES 4         // j split into 4 slices of 128 packs

__device__ float g_sde[B_DIM * H_DIM];
__device__ float g_cm[B_DIM][3];

__device__ __forceinline__ u64 pk2(float lo, float hi) {
    u64 r; asm("mov.b64 %0, {%1,%2};" : "=l"(r) : "f"(lo), "f"(hi)); return r;
}
__device__ __forceinline__ u64 ffma2(u64 a, u64 b, u64 c) {
    u64 d; asm("fma.rn.f32x2 %0, %1, %2, %3;" : "=l"(d) : "l"(a), "l"(b), "l"(c)); return d;
}
__device__ __forceinline__ void unpk2(u64 v, float& lo, float& hi) {
    asm("mov.b64 {%0,%1}, %2;" : "=f"(lo), "=f"(hi) : "l"(v));
}

// One block per (b,h), 512 threads. Thread layout: g = t&127 owns rows
// 8g..8g+7; slice = t>>7 scans j-packs [slice*128, slice*128+128).
// Each 32B broadcast LDS pair now serves 16 pair-distances (2 B/pair),
// pushing the kernel from smem-bus-bound to fma-pipe-bound.
// sde = 2*mean_i min_j |refl_i - s_j|^2  (reflection isometry collapses
// both chamfer directions). h==0 blocks also emit the batch centroid.
__global__ void __launch_bounds__(512, 1)
chamfer_kernel(const float* __restrict__ y_pred, const float* __restrict__ sp)
{
    const int bh = blockIdx.x;
    const int b  = bh >> 4;
    const int t  = threadIdx.x;
    const int g  = t & (GROUPS - 1);
    const int slice = t >> 7;

    const float* yp = y_pred + 4 * bh;
    float nx = yp[0], ny = yp[1], nz = yp[2], pd = yp[3];
    float inv = 1.0f / sqrtf(nx * nx + ny * ny + nz * nz);
    nx *= inv; ny *= inv; nz *= inv;

    __shared__ ulonglong2 shA[512];   // {x0,x1, y0,y1} packed point pairs (8KB)
    __shared__ ulonglong2 shB[512];   // {z0,z1, ss0,ss1}                  (8KB)
    __shared__ float red[GROUPS];
    __shared__ float ws[48];          // centroid warp partials (x|y|z * 16 warps)

    const float* pb = sp + b * (N_PTS * 3);

    // ---- pack point table: thread t packs points 2t, 2t+1 ----
    {
        const float2* pb2 = (const float2*)pb;
        float2 q0 = pb2[3 * t + 0];
        float2 q1 = pb2[3 * t + 1];
        float2 q2 = pb2[3 * t + 2];
        float x0 = q0.x, y0 = q0.y, z0 = q1.x;
        float x1 = q1.y, y1 = q2.x, z1 = q2.y;
        float s0 = fmaf(x0, x0, fmaf(y0, y0, z0 * z0));
        float s1 = fmaf(x1, x1, fmaf(y1, y1, z1 * z1));
        float4 va; va.x = x0; va.y = x1; va.z = y0; va.w = y1;
        float4 vb; vb.x = z0; vb.y = z1; vb.z = s0; vb.w = s1;
        ((float4*)shA)[t] = va;
        ((float4*)shB)[t] = vb;

        // centroid partials (h==0 blocks only)
        if ((bh & 15) == 0) {
            float cx = x0 + x1, cy = y0 + y1, cz = z0 + z1;
            #pragma unroll
            for (int o = 16; o > 0; o >>= 1) {
                cx += __shfl_down_sync(0xffffffffu, cx, o);
                cy += __shfl_down_sync(0xffffffffu, cy, o);
                cz += __shfl_down_sync(0xffffffffu, cz, o);
            }
            if ((t & 31) == 0) {
                int w = t >> 5;
                ws[w] = cx; ws[16 + w] = cy; ws[32 + w] = cz;
            }
        }
    }

    // ---- reflect owned rows 8g..8g+7 ----
    u64 ax[ROWS], ay[ROWS], az[ROWS];
    float rr[ROWS];
    {
        const float* pr = pb + 3 * ROWS * g;
        #pragma unroll
        for (int i = 0; i < ROWS; ++i) {
            float sx = pr[3 * i + 0], sy = pr[3 * i + 1], sz = pr[3 * i + 2];
            float p = fmaf(nx, sx, fmaf(ny, sy, fmaf(nz, sz, pd)));
            float rx = fmaf(-2.0f * p, nx, sx);
            float ry = fmaf(-2.0f * p, ny, sy);
            float rz = fmaf(-2.0f * p, nz, sz);
            rr[i] = fmaf(rx, rx, fmaf(ry, ry, rz * rz));
            ax[i] = pk2(-2.0f * rx, -2.0f * rx);
            ay[i] = pk2(-2.0f * ry, -2.0f * ry);
            az[i] = pk2(-2.0f * rz, -2.0f * rz);
        }
    }

    __syncthreads();

    // centroid finalize (cheap; only 8 blocks take this path)
    if ((bh & 15) == 0 && t == 0) {
        float cx = 0, cy = 0, cz = 0;
        #pragma unroll
        for (int w = 0; w < 16; ++w) { cx += ws[w]; cy += ws[16 + w]; cz += ws[32 + w]; }
        g_cm[b][0] = cx * (1.0f / N_PTS);
        g_cm[b][1] = cy * (1.0f / N_PTS);
        g_cm[b][2] = cz * (1.0f / N_PTS);
    }

    const float INF = __int_as_float(0x7f800000);
    float m0[ROWS], m1[ROWS];
    #pragma unroll
    for (int i = 0; i < ROWS; ++i) { m0[i] = INF; m1[i] = INF; }

    const int jbeg = slice << 7;
    #pragma unroll 2
    for (int jj = 0; jj < 128; ++jj) {
        const int j = jbeg + jj;
        ulonglong2 A  = shA[j];   // {x0,x1},{y0,y1}
        ulonglong2 Bv = shB[j];   // {z0,z1},{ss0,ss1}
        #pragma unroll
        for (int i = 0; i < ROWS; ++i) {
            u64 v = ffma2(az[i], Bv.x, Bv.y);
            v = ffma2(ay[i], A.y, v);
            v = ffma2(ax[i], A.x, v);
            float vl, vh; unpk2(v, vl, vh);
            m0[i] = fminf(m0[i], vl);
            m1[i] = fminf(m1[i], vh);
        }
    }

    __syncthreads();

    // slices 1..3 publish per-row partial mins into (now dead) shA/shB space
    float* pmin = (float*)shA;    // 12KB needed, 16KB available
    if (slice > 0) {
        float4* dst = (float4*)(pmin + ((slice - 1) * GROUPS + g) * ROWS);
        float4 a; a.x = fminf(m0[0], m1[0]); a.y = fminf(m0[1], m1[1]);
                  a.z = fminf(m0[2], m1[2]); a.w = fminf(m0[3], m1[3]);
        float4 c; c.x = fminf(m0[4], m1[4]); c.y = fminf(m0[5], m1[5]);
                  c.z = fminf(m0[6], m1[6]); c.w = fminf(m0[7], m1[7]);
        dst[0] = a; dst[1] = c;
    }
    __syncthreads();

    if (slice == 0) {
        const float4* p1 = (const float4*)(pmin + (0 * GROUPS + g) * ROWS);
        const float4* p2 = (const float4*)(pmin + (1 * GROUPS + g) * ROWS);
        const float4* p3 = (const float4*)(pmin + (2 * GROUPS + g) * ROWS);
        float4 a1 = p1[0], c1 = p1[1];
        float4 a2 = p2[0], c2 = p2[1];
        float4 a3 = p3[0], c3 = p3[1];
        float acc = 0.0f;
        acc += rr[0] + fminf(fminf(m0[0], m1[0]), fminf(a1.x, fminf(a2.x, a3.x)));
        acc += rr[1] + fminf(fminf(m0[1], m1[1]), fminf(a1.y, fminf(a2.y, a3.y)));
        acc += rr[2] + fminf(fminf(m0[2], m1[2]), fminf(a1.z, fminf(a2.z, a3.z)));
        acc += rr[3] + fminf(fminf(m0[3], m1[3]), fminf(a1.w, fminf(a2.w, a3.w)));
        acc += rr[4] + fminf(fminf(m0[4], m1[4]), fminf(c1.x, fminf(c2.x, c3.x)));
        acc += rr[5] + fminf(fminf(m0[5], m1[5]), fminf(c1.y, fminf(c2.y, c3.y)));
        acc += rr[6] + fminf(fminf(m0[6], m1[6]), fminf(c1.z, fminf(c2.z, c3.z)));
        acc += rr[7] + fminf(fminf(m0[7], m1[7]), fminf(c1.w, fminf(c2.w, c3.w)));
        red[g] = acc;
    }
    __syncthreads();

    // deterministic reduce over 128 group sums
    if (t < 64) red[t] += red[t + 64];
    __syncthreads();
    if (t < 32) {
        float v = red[t] + red[t + 32];
        v += __shfl_down_sync(0xffffffffu, v, 16);
        v += __shfl_down_sync(0xffffffffu, v, 8);
        v += __shfl_down_sync(0xffffffffu, v, 4);
        v += __shfl_down_sync(0xffffffffu, v, 2);
        v += __shfl_down_sync(0xffffffffu, v, 1);
        if (t == 0) g_sde[bh] = 2.0f * (v * (1.0f / 1024.0f));
    }
}

// One block, 128 threads: thread t = (b,h). Reads only g_sde, g_cm, y_pred.
__global__ void __launch_bounds__(128, 1)
final_kernel(const float* __restrict__ y_pred, float* __restrict__ out)
{
    const int t  = threadIdx.x;
    const int eb = t >> 4;
    const int eh = t & 15;

    __shared__ float hnx[128], hny[128], hnz[128], hsd[128], hkey[128];

    const float* ypp = y_pred + 4 * t;
    float nx = ypp[0], ny = ypp[1], nz = ypp[2], pd = ypp[3];
    float iv = 1.0f / sqrtf(nx * nx + ny * ny + nz * nz);
    nx *= iv; ny *= iv; nz *= iv;
    float sde = g_sde[t];
    hnx[t] = nx; hny[t] = ny; hnz[t] = nz; hsd[t] = sde;
    __syncthreads();

    const int base = eb * H_DIM;
    float mn = hsd[base], mx = hsd[base];
    #pragma unroll
    for (int g2 = 1; g2 < H_DIM; ++g2) {
        mn = fminf(mn, hsd[base + g2]); mx = fmaxf(mx, hsd[base + g2]);
    }
    float conf = 1.0f - (sde - mn) / fabsf(mx - mn);

    bool valid = (sde <= 10.0f);
    bool any = false;
    #pragma unroll
    for (int g2 = 0; g2 < H_DIM; ++g2) {
        if (g2 == eh) continue;
        float c = nx * hnx[base + g2] + ny * hny[base + g2] + nz * hnz[base + g2];
        c = fminf(1.0f, fmaxf(-1.0f, c));
        float ang = acosf(c) * 57.29577951308232f;
        bool close = (ang < 30.0f) || ((180.0f - ang) < 30.0f);
        if (close && (hsd[base + g2] <= 10.0f) && (sde >= hsd[base + g2])) any = true;
    }
    bool keep = valid && !any;
    hkey[t] = keep ? conf : __int_as_float(0xff800000);
    __syncthreads();

    float key = hkey[t];
    int rank = 0;
    #pragma unroll
    for (int g2 = 0; g2 < H_DIM; ++g2) {
        float kg = hkey[base + g2];
        if (kg > key || (kg == key && g2 < eh)) rank++;
    }
    float* o = out + (base + rank) * 8;
    if (keep) {
        float cx = g_cm[eb][0], cy = g_cm[eb][1], cz = g_cm[eb][2];
        float pj = fmaf(nx, cx, fmaf(ny, cy, fmaf(nz, cz, pd)));
        o[0] = nx; o[1] = ny; o[2] = nz;
        o[3] = cx - pj * nx;
        o[4] = cy - pj * ny;
        o[5] = cz - pj * nz;
        o[6] = conf;
        o[7] = sde;
    } else {
        #pragma unroll
        for (int c = 0; c < 8; ++c) o[c] = 0.0f;
    }
}

extern "C" void kernel_launch(void* const* d_in, const int* in_sizes, int n_in,
                              void* d_out, int out_size)
{
    const float* y_pred = (const float*)d_in[0];   // (8,16,4)
    const float* sp     = (const float*)d_in[1];   // (8,1024,3)
    float* out          = (float*)d_out;           // (8,16,8)

    chamfer_kernel<<<B_DIM * H_DIM, 512>>>(y_pred, sp);
    final_kernel<<<1, 128>>>(y_pred, out);
}

// round 5
// speedup vs baseline: 1.1304x; 1.1304x over previous
#include <cuda_runtime.h>
#include <math.h>

typedef unsigned long long u64;

#define B_DIM 8
#define H_DIM 16
#define N_PTS 1024
#define ROWS  8          // rows per thread
#define GROUPS 128       // 128 groups * 8 rows = 1024 rows
#define SLICES 4         // j split into 4 slices of 128 packs

__device__ float g_sde[B_DIM * H_DIM];
__device__ float g_cm[B_DIM][3];

__device__ __forceinline__ u64 pk2(float lo, float hi) {
    u64 r; asm("mov.b64 %0, {%1,%2};" : "=l"(r) : "f"(lo), "f"(hi)); return r;
}
__device__ __forceinline__ u64 ffma2(u64 a, u64 b, u64 c) {
    u64 d; asm("fma.rn.f32x2 %0, %1, %2, %3;" : "=l"(d) : "l"(a), "l"(b), "l"(c)); return d;
}
__device__ __forceinline__ void unpk2(u64 v, float& lo, float& hi) {
    asm("mov.b64 {%0,%1}, %2;" : "=f"(lo), "=f"(hi) : "l"(v));
}

// One block per (b,h), 512 threads. g = t&127 owns rows 8g..8g+7;
// slice = t>>7 scans j-packs [slice*128, slice*128+128).
// sde = 2*mean_i min_j |refl_i - s_j|^2 (reflection isometry collapses both
// chamfer directions). Inner loop is software-pipelined: next j-pack is
// prefetched into registers while the current pack's 8 row-chains execute.
__global__ void __launch_bounds__(512, 1)
chamfer_kernel(const float* __restrict__ y_pred, const float* __restrict__ sp)
{
    const int bh = blockIdx.x;
    const int b  = bh >> 4;
    const int t  = threadIdx.x;
    const int g  = t & (GROUPS - 1);
    const int slice = t >> 7;

    const float* yp = y_pred + 4 * bh;
    float nx = yp[0], ny = yp[1], nz = yp[2], pd = yp[3];
    float inv = 1.0f / sqrtf(nx * nx + ny * ny + nz * nz);
    nx *= inv; ny *= inv; nz *= inv;

    __shared__ ulonglong2 shA[513];   // {x0,x1, y0,y1} packed point pairs (+1 pad for prefetch)
    __shared__ ulonglong2 shB[513];   // {z0,z1, ss0,ss1}
    __shared__ float red[GROUPS];
    __shared__ float ws[48];          // centroid warp partials

    const float* pb = sp + b * (N_PTS * 3);

    // ---- pack point table: thread t packs points 2t, 2t+1 ----
    {
        const float2* pb2 = (const float2*)pb;
        float2 q0 = pb2[3 * t + 0];
        float2 q1 = pb2[3 * t + 1];
        float2 q2 = pb2[3 * t + 2];
        float x0 = q0.x, y0 = q0.y, z0 = q1.x;
        float x1 = q1.y, y1 = q2.x, z1 = q2.y;
        float s0 = fmaf(x0, x0, fmaf(y0, y0, z0 * z0));
        float s1 = fmaf(x1, x1, fmaf(y1, y1, z1 * z1));
        float4 va; va.x = x0; va.y = x1; va.z = y0; va.w = y1;
        float4 vb; vb.x = z0; vb.y = z1; vb.z = s0; vb.w = s1;
        ((float4*)shA)[t] = va;
        ((float4*)shB)[t] = vb;
        if (t == 0) {                 // pad entry: prefetch target on last iter (value unused)
            ((float4*)shA)[512] = va;
            ((float4*)shB)[512] = vb;
        }

        // centroid partials (h==0 blocks only)
        if ((bh & 15) == 0) {
            float cx = x0 + x1, cy = y0 + y1, cz = z0 + z1;
            #pragma unroll
            for (int o = 16; o > 0; o >>= 1) {
                cx += __shfl_down_sync(0xffffffffu, cx, o);
                cy += __shfl_down_sync(0xffffffffu, cy, o);
                cz += __shfl_down_sync(0xffffffffu, cz, o);
            }
            if ((t & 31) == 0) {
                int w = t >> 5;
                ws[w] = cx; ws[16 + w] = cy; ws[32 + w] = cz;
            }
        }
    }

    // ---- reflect owned rows 8g..8g+7 ----
    u64 ax[ROWS], ay[ROWS], az[ROWS];
    float rr[ROWS];
    {
        const float* pr = pb + 3 * ROWS * g;
        #pragma unroll
        for (int i = 0; i < ROWS; ++i) {
            float sx = pr[3 * i + 0], sy = pr[3 * i + 1], sz = pr[3 * i + 2];
            float p = fmaf(nx, sx, fmaf(ny, sy, fmaf(nz, sz, pd)));
            float rx = fmaf(-2.0f * p, nx, sx);
            float ry = fmaf(-2.0f * p, ny, sy);
            float rz = fmaf(-2.0f * p, nz, sz);
            rr[i] = fmaf(rx, rx, fmaf(ry, ry, rz * rz));
            ax[i] = pk2(-2.0f * rx, -2.0f * rx);
            ay[i] = pk2(-2.0f * ry, -2.0f * ry);
            az[i] = pk2(-2.0f * rz, -2.0f * rz);
        }
    }

    __syncthreads();

    if ((bh & 15) == 0 && t == 0) {
        float cx = 0, cy = 0, cz = 0;
        #pragma unroll
        for (int w = 0; w < 16; ++w) { cx += ws[w]; cy += ws[16 + w]; cz += ws[32 + w]; }
        g_cm[b][0] = cx * (1.0f / N_PTS);
        g_cm[b][1] = cy * (1.0f / N_PTS);
        g_cm[b][2] = cz * (1.0f / N_PTS);
    }

    const float INF = __int_as_float(0x7f800000);
    float m0[ROWS], m1[ROWS];
    #pragma unroll
    for (int i = 0; i < ROWS; ++i) { m0[i] = INF; m1[i] = INF; }

    const int jbeg = slice << 7;

    // software-pipelined mainloop: prefetch pack jj+1 while computing jj
    ulonglong2 A  = shA[jbeg];
    ulonglong2 Bv = shB[jbeg];
    #pragma unroll 4
    for (int jj = 0; jj < 128; ++jj) {
        ulonglong2 An = shA[jbeg + jj + 1];
        ulonglong2 Bn = shB[jbeg + jj + 1];
        #pragma unroll
        for (int i = 0; i < ROWS; ++i) {
            u64 v = ffma2(az[i], Bv.x, Bv.y);
            v = ffma2(ay[i], A.y, v);
            v = ffma2(ax[i], A.x, v);
            float vl, vh; unpk2(v, vl, vh);
            m0[i] = fminf(m0[i], vl);
            m1[i] = fminf(m1[i], vh);
        }
        A = An; Bv = Bn;
    }

    __syncthreads();

    // slices 1..3 publish per-row partial mins into dead shA space
    float* pmin = (float*)shA;
    if (slice > 0) {
        float4* dst = (float4*)(pmin + ((slice - 1) * GROUPS + g) * ROWS);
        float4 a; a.x = fminf(m0[0], m1[0]); a.y = fminf(m0[1], m1[1]);
                  a.z = fminf(m0[2], m1[2]); a.w = fminf(m0[3], m1[3]);
        float4 c; c.x = fminf(m0[4], m1[4]); c.y = fminf(m0[5], m1[5]);
                  c.z = fminf(m0[6], m1[6]); c.w = fminf(m0[7], m1[7]);
        dst[0] = a; dst[1] = c;
    }
    __syncthreads();

    if (slice == 0) {
        const float4* p1 = (const float4*)(pmin + (0 * GROUPS + g) * ROWS);
        const float4* p2 = (const float4*)(pmin + (1 * GROUPS + g) * ROWS);
        const float4* p3 = (const float4*)(pmin + (2 * GROUPS + g) * ROWS);
        float4 a1 = p1[0], c1 = p1[1];
        float4 a2 = p2[0], c2 = p2[1];
        float4 a3 = p3[0], c3 = p3[1];
        float acc = 0.0f;
        acc += rr[0] + fminf(fminf(m0[0], m1[0]), fminf(a1.x, fminf(a2.x, a3.x)));
        acc += rr[1] + fminf(fminf(m0[1], m1[1]), fminf(a1.y, fminf(a2.y, a3.y)));
        acc += rr[2] + fminf(fminf(m0[2], m1[2]), fminf(a1.z, fminf(a2.z, a3.z)));
        acc += rr[3] + fminf(fminf(m0[3], m1[3]), fminf(a1.w, fminf(a2.w, a3.w)));
        acc += rr[4] + fminf(fminf(m0[4], m1[4]), fminf(c1.x, fminf(c2.x, c3.x)));
        acc += rr[5] + fminf(fminf(m0[5], m1[5]), fminf(c1.y, fminf(c2.y, c3.y)));
        acc += rr[6] + fminf(fminf(m0[6], m1[6]), fminf(c1.z, fminf(c2.z, c3.z)));
        acc += rr[7] + fminf(fminf(m0[7], m1[7]), fminf(c1.w, fminf(c2.w, c3.w)));
        red[g] = acc;
    }
    __syncthreads();

    if (t < 64) red[t] += red[t + 64];
    __syncthreads();
    if (t < 32) {
        float v = red[t] + red[t + 32];
        v += __shfl_down_sync(0xffffffffu, v, 16);
        v += __shfl_down_sync(0xffffffffu, v, 8);
        v += __shfl_down_sync(0xffffffffu, v, 4);
        v += __shfl_down_sync(0xffffffffu, v, 2);
        v += __shfl_down_sync(0xffffffffu, v, 1);
        if (t == 0) g_sde[bh] = 2.0f * (v * (1.0f / 1024.0f));
    }
}

// One block, 128 threads: thread t = (b,h). acosf eliminated:
// (ang<30 || 180-ang<30)  <=>  |cos| > cos(30 deg)   (acos is monotone).
__global__ void __launch_bounds__(128, 1)
final_kernel(const float* __restrict__ y_pred, float* __restrict__ out)
{
    const int t  = threadIdx.x;
    const int eb = t >> 4;
    const int eh = t & 15;

    __shared__ float hnx[128], hny[128], hnz[128], hsd[128], hkey[128];

    const float* ypp = y_pred + 4 * t;
    float nx = ypp[0], ny = ypp[1], nz = ypp[2], pd = ypp[3];
    float iv = 1.0f / sqrtf(nx * nx + ny * ny + nz * nz);
    nx *= iv; ny *= iv; nz *= iv;
    float sde = g_sde[t];
    hnx[t] = nx; hny[t] = ny; hnz[t] = nz; hsd[t] = sde;
    __syncthreads();

    const int base = eb * H_DIM;
    float mn = hsd[base], mx = hsd[base];
    #pragma unroll
    for (int g2 = 1; g2 < H_DIM; ++g2) {
        mn = fminf(mn, hsd[base + g2]); mx = fmaxf(mx, hsd[base + g2]);
    }
    float conf = 1.0f - (sde - mn) / fabsf(mx - mn);

    const float COS30 = 0.86602540378443864676f;
    bool valid = (sde <= 10.0f);
    bool any = false;
    #pragma unroll
    for (int g2 = 0; g2 < H_DIM; ++g2) {
        if (g2 == eh) continue;
        float c = nx * hnx[base + g2] + ny * hny[base + g2] + nz * hnz[base + g2];
        c = fminf(1.0f, fmaxf(-1.0f, c));
        bool close = fabsf(c) > COS30;
        if (close && (hsd[base + g2] <= 10.0f) && (sde >= hsd[base + g2])) any = true;
    }
    bool keep = valid && !any;
    hkey[t] = keep ? conf : __int_as_float(0xff800000);
    __syncthreads();

    float key = hkey[t];
    int rank = 0;
    #pragma unroll
    for (int g2 = 0; g2 < H_DIM; ++g2) {
        float kg = hkey[base + g2];
        if (kg > key || (kg == key && g2 < eh)) rank++;
    }
    float* o = out + (base + rank) * 8;
    if (keep) {
        float cx = g_cm[eb][0], cy = g_cm[eb][1], cz = g_cm[eb][2];
        float pj = fmaf(nx, cx, fmaf(ny, cy, fmaf(nz, cz, pd)));
        o[0] = nx; o[1] = ny; o[2] = nz;
        o[3] = cx - pj * nx;
        o[4] = cy - pj * ny;
        o[5] = cz - pj * nz;
        o[6] = conf;
        o[7] = sde;
    } else {
        #pragma unroll
        for (int c = 0; c < 8; ++c) o[c] = 0.0f;
    }
}

extern "C" void kernel_launch(void* const* d_in, const int* in_sizes, int n_in,
                              void* d_out, int out_size)
{
    const float* y_pred = (const float*)d_in[0];   // (8,16,4)
    const float* sp     = (const float*)d_in[1];   // (8,1024,3)
    float* out          = (float*)d_out;           // (8,16,8)

    chamfer_kernel<<<B_DIM * H_DIM, 512>>>(y_pred, sp);
    final_kernel<<<1, 128>>>(y_pred, out);
}